// round 3
// baseline (speedup 1.0000x reference)
#include <cuda_runtime.h>
#include <math.h>

#define NN 100000
#define NE 3200000
#define FIN 128
#define RS 16          // padded row stride for 10-dim vectors
#define NB 1000
#define NBLK 98        // ceil(NN / 1024) for the two-level scan

// Scratch (allocation-free: __device__ globals, zero-init at load)
static __device__ float g_xa[NN * RS];    // x @ W1[:128]   (self part)
static __device__ float g_xb[NN * RS];    // x @ W1[128:]   (neighbor part)
static __device__ float g_h1a[NN * RS];   // h1 @ W2[:10]
static __device__ float g_h1b[NN * RS];   // h1 @ W2[10:]
static __device__ float g_pool[NB * RS];  // batch pool sums ([10] = node count)
static __device__ int   g_deg[NN];        // in-degree
static __device__ int   g_start[NN];      // CSR row starts
static __device__ int   g_cursor[NN];     // scatter cursors
static __device__ int   g_adj[NE];        // CSR adjacency: src ids grouped by dst
static __device__ int   g_bsum[NBLK];     // per-block degree sums -> offsets

// ---------------------------------------------------------------------------
__global__ void k_zero() {
    int tid = blockIdx.x * blockDim.x + threadIdx.x;
    int stride = gridDim.x * blockDim.x;
    for (int i = tid; i < NN; i += stride) g_deg[i] = 0;
    for (int i = tid; i < NB * RS; i += stride) g_pool[i] = 0.f;
}

// ---------------------------------------------------------------------------
// CSR build: histogram -> 2-level exclusive scan -> scatter
__global__ __launch_bounds__(256) void k_hist(const int* __restrict__ dst) {
    int t = blockIdx.x * blockDim.x + threadIdx.x;
    if (t >= NE / 2) return;
    int2 d2 = __ldg((const int2*)dst + t);
    atomicAdd(&g_deg[d2.x], 1);
    atomicAdd(&g_deg[d2.y], 1);
}

__global__ __launch_bounds__(256) void k_scanA() {   // per-block (1024-node) sums
    int t = threadIdx.x, blk = blockIdx.x;
    int base = blk * 1024 + t * 4;
    int s = 0;
#pragma unroll
    for (int j = 0; j < 4; j++) { int i = base + j; if (i < NN) s += g_deg[i]; }
#pragma unroll
    for (int off = 16; off; off >>= 1) s += __shfl_xor_sync(0xffffffffu, s, off);
    __shared__ int ws[8];
    if ((t & 31) == 0) ws[t >> 5] = s;
    __syncthreads();
    if (t == 0) {
        int r = 0;
#pragma unroll
        for (int i = 0; i < 8; i++) r += ws[i];
        g_bsum[blk] = r;
    }
}

__global__ void k_scanB() {                          // exclusive scan of 98 block sums
    int t = threadIdx.x;                             // 128 threads
    int v = (t < NBLK) ? g_bsum[t] : 0;
    int lane = t & 31, wid = t >> 5;
    int incl = v;
#pragma unroll
    for (int off = 1; off < 32; off <<= 1) {
        int u = __shfl_up_sync(0xffffffffu, incl, off);
        if (lane >= off) incl += u;
    }
    __shared__ int ws[4], wo[4];
    if (lane == 31) ws[wid] = incl;
    __syncthreads();
    if (t == 0) { int r = 0; for (int i = 0; i < 4; i++) { wo[i] = r; r += ws[i]; } }
    __syncthreads();
    int excl = wo[wid] + incl - v;
    if (t < NBLK) g_bsum[t] = excl;
}

__global__ __launch_bounds__(256) void k_scanC() {   // full exclusive scan -> start/cursor
    int t = threadIdx.x, blk = blockIdx.x;
    int base = blk * 1024 + t * 4;
    int vals[4]; int tsum = 0;
#pragma unroll
    for (int j = 0; j < 4; j++) {
        int i = base + j;
        vals[j] = (i < NN) ? g_deg[i] : 0;
        tsum += vals[j];
    }
    int lane = t & 31, wid = t >> 5;
    int incl = tsum;
#pragma unroll
    for (int off = 1; off < 32; off <<= 1) {
        int u = __shfl_up_sync(0xffffffffu, incl, off);
        if (lane >= off) incl += u;
    }
    __shared__ int ws[8], wo[8];
    if (lane == 31) ws[wid] = incl;
    __syncthreads();
    if (t == 0) { int r = 0; for (int i = 0; i < 8; i++) { wo[i] = r; r += ws[i]; } }
    __syncthreads();
    int excl = g_bsum[blk] + wo[wid] + incl - tsum;
#pragma unroll
    for (int j = 0; j < 4; j++) {
        int i = base + j;
        if (i < NN) { g_start[i] = excl; g_cursor[i] = excl; excl += vals[j]; }
    }
}

__global__ __launch_bounds__(256) void k_scatter(const int* __restrict__ src,
                                                 const int* __restrict__ dst) {
    int t = blockIdx.x * blockDim.x + threadIdx.x;
    if (t >= NE / 2) return;
    int2 s2 = __ldg((const int2*)src + t);
    int2 d2 = __ldg((const int2*)dst + t);
    int p0 = atomicAdd(&g_cursor[d2.x], 1);
    int p1 = atomicAdd(&g_cursor[d2.y], 1);
    g_adj[p0] = s2.x;
    g_adj[p1] = s2.y;
}

// ---------------------------------------------------------------------------
// Layer-1 projection: warp per 8 nodes, weights resident in registers,
// register-permuted split reduction (30 shuffles/node).
__global__ __launch_bounds__(256) void k_gemm1(const float* __restrict__ x,
                                               const float* __restrict__ W1) {
    const int lane = threadIdx.x & 31;
    const int warp = (blockIdx.x * blockDim.x + threadIdx.x) >> 5;
    if (warp >= NN / 8) return;
    const int b4 = (lane >> 4) & 1;
    const int b3 = (lane >> 3) & 1;

    float w[4][20];
#pragma unroll
    for (int j = 0; j < 4; j++) {
        int f = lane * 4 + j;
#pragma unroll
        for (int r = 0; r < 20; r++) {
            int o = (r < 10) ? (10 * b4 + ((r + 5 * b3) % 10))
                             : (10 * (1 - b4) + (((r - 10) + 5 * b3) % 10));
            w[j][r] = __ldg((o < 10) ? &W1[f * 10 + o] : &W1[(f + 128) * 10 + (o - 10)]);
        }
    }

    const int nbase = warp * 8;
#pragma unroll 1
    for (int ni = 0; ni < 8; ni++) {
        int n = nbase + ni;
        float4 xv = *(const float4*)(x + (size_t)n * FIN + lane * 4);
        float xs[4] = {xv.x, xv.y, xv.z, xv.w};
        float acc[20];
#pragma unroll
        for (int r = 0; r < 20; r++) acc[r] = 0.f;
#pragma unroll
        for (int j = 0; j < 4; j++)
#pragma unroll
            for (int r = 0; r < 20; r++) acc[r] += xs[j] * w[j][r];

#pragma unroll
        for (int i = 0; i < 10; i++) acc[i] += __shfl_xor_sync(0xffffffffu, acc[i + 10], 16);
#pragma unroll
        for (int i = 0; i < 5; i++)  acc[i] += __shfl_xor_sync(0xffffffffu, acc[i + 5], 8);
#pragma unroll
        for (int off = 4; off; off >>= 1)
#pragma unroll
            for (int i = 0; i < 5; i++)
                acc[i] += __shfl_xor_sync(0xffffffffu, acc[i], off);

        if ((lane & 7) == 0) {
            if (lane == 0) {
#pragma unroll
                for (int i = 0; i < 5; i++) g_xa[n * RS + i] = acc[i];
            } else if (lane == 8) {
#pragma unroll
                for (int i = 0; i < 5; i++) g_xa[n * RS + 5 + i] = acc[i];
            } else if (lane == 16) {
#pragma unroll
                for (int i = 0; i < 5; i++) g_xb[n * RS + i] = acc[i];
            } else {
#pragma unroll
                for (int i = 0; i < 5; i++) g_xb[n * RS + 5 + i] = acc[i];
            }
        }
    }
}

// ---------------------------------------------------------------------------
__device__ __forceinline__ void red_v4(float* p, float a, float b, float c, float d) {
    asm volatile("red.global.add.v4.f32 [%0], {%1,%2,%3,%4};"
                 :: "l"(p), "f"(a), "f"(b), "f"(c), "f"(d) : "memory");
}

// Pull-mode aggregation, warp per node, fused epilogue. No float atomics on agg.
// PASS 0: agg = mean(xb[adj]); h1 = relu(xa + agg); h1a/h1b = h1 @ W2 halves.
// PASS 1: agg = mean(h1b[adj]); h2 = h1a + agg; pool[batch[n]] += h2 (3 REDs).
template <int PASS>
__global__ __launch_bounds__(256) void k_aggr(const float* __restrict__ W2,
                                              const int* __restrict__ batch) {
    const int lane = threadIdx.x & 31;
    const int n = (blockIdx.x * blockDim.x + threadIdx.x) >> 5;
    if (n >= NN) return;

    // (pass 0) preload this lane's W2 column while gathers are in flight
    float wcol[10];
    if (PASS == 0 && lane < 20) {
        int col = lane % 10, off = (lane < 10) ? 0 : 10;
#pragma unroll
        for (int k = 0; k < 10; k++) wcol[k] = __ldg(&W2[(k + off) * 10 + col]);
    }

    const int start = g_start[n];
    const int deg = g_deg[n];
    const float* buf = (PASS == 0) ? g_xb : g_h1b;

    float acc[10];
#pragma unroll
    for (int i = 0; i < 10; i++) acc[i] = 0.f;
    for (int i = lane; i < deg; i += 32) {
        int s = __ldg(&g_adj[start + i]);
        const float4* vp = (const float4*)(buf + (size_t)s * RS);
        float4 v0 = __ldg(vp), v1 = __ldg(vp + 1);
        float2 v2 = __ldg((const float2*)(vp + 2));
        acc[0] += v0.x; acc[1] += v0.y; acc[2] += v0.z; acc[3] += v0.w;
        acc[4] += v1.x; acc[5] += v1.y; acc[6] += v1.z; acc[7] += v1.w;
        acc[8] += v2.x; acc[9] += v2.y;
    }
#pragma unroll
    for (int off = 16; off; off >>= 1)
#pragma unroll
        for (int i = 0; i < 10; i++)
            acc[i] += __shfl_xor_sync(0xffffffffu, acc[i], off);

    const float inv = deg > 0 ? 1.f / (float)deg : 0.f;

    if (PASS == 0) {
        const float4* xr = (const float4*)(g_xa + (size_t)n * RS);
        float4 x0 = __ldg(xr), x1 = __ldg(xr + 1);
        float2 x2 = __ldg((const float2*)(xr + 2));
        float h[10];
        h[0] = fmaxf(x0.x + acc[0] * inv, 0.f); h[1] = fmaxf(x0.y + acc[1] * inv, 0.f);
        h[2] = fmaxf(x0.z + acc[2] * inv, 0.f); h[3] = fmaxf(x0.w + acc[3] * inv, 0.f);
        h[4] = fmaxf(x1.x + acc[4] * inv, 0.f); h[5] = fmaxf(x1.y + acc[5] * inv, 0.f);
        h[6] = fmaxf(x1.z + acc[6] * inv, 0.f); h[7] = fmaxf(x1.w + acc[7] * inv, 0.f);
        h[8] = fmaxf(x2.x + acc[8] * inv, 0.f); h[9] = fmaxf(x2.y + acc[9] * inv, 0.f);
        if (lane < 20) {
            float o = 0.f;
#pragma unroll
            for (int k = 0; k < 10; k++) o += h[k] * wcol[k];
            if (lane < 10) g_h1a[(size_t)n * RS + lane] = o;
            else           g_h1b[(size_t)n * RS + lane - 10] = o;
        }
    } else {
        if (lane == 0) {
            const float4* ar = (const float4*)(g_h1a + (size_t)n * RS);
            float4 a0 = __ldg(ar), a1 = __ldg(ar + 1);
            float2 a2 = __ldg((const float2*)(ar + 2));
            float h0 = a0.x + acc[0] * inv, h1 = a0.y + acc[1] * inv;
            float h2 = a0.z + acc[2] * inv, h3 = a0.w + acc[3] * inv;
            float h4 = a1.x + acc[4] * inv, h5 = a1.y + acc[5] * inv;
            float h6 = a1.z + acc[6] * inv, h7 = a1.w + acc[7] * inv;
            float h8 = a2.x + acc[8] * inv, h9 = a2.y + acc[9] * inv;
            float* pp = g_pool + __ldg(&batch[n]) * RS;
            red_v4(pp,     h0, h1, h2, h3);
            red_v4(pp + 4, h4, h5, h6, h7);
            red_v4(pp + 8, h8, h9, 1.f, 0.f);   // node count rides pad slot 10
        }
    }
}

// ---------------------------------------------------------------------------
__global__ void k_head(const float* __restrict__ Wfc, float* __restrict__ out) {
    int b = blockIdx.x * blockDim.x + threadIdx.x;
    if (b >= NB) return;
    float inv = 1.f / fmaxf(g_pool[b * RS + 10], 1.f);
    float v = 0.f;
#pragma unroll
    for (int o = 0; o < 10; o++)
        v += g_pool[b * RS + o] * inv * __ldg(&Wfc[o]);
    out[b] = 1.f / (1.f + expf(-v));
}

// ---------------------------------------------------------------------------
extern "C" void kernel_launch(void* const* d_in, const int* in_sizes, int n_in,
                              void* d_out, int out_size) {
    const float* x     = (const float*)d_in[0];
    const int*   ei    = (const int*)d_in[1];   // [2, E]
    const int*   batch = (const int*)d_in[2];
    const float* W1    = (const float*)d_in[3]; // [256,10]
    const float* W2    = (const float*)d_in[4]; // [20,10]
    const float* Wfc   = (const float*)d_in[5]; // [10,1]
    float* out = (float*)d_out;

    const int* src = ei;
    const int* dst = ei + NE;

    k_zero<<<256, 256>>>();
    k_gemm1<<<(NN / 8 + 7) / 8, 256>>>(x, W1);
    k_hist<<<(NE / 2 + 255) / 256, 256>>>(dst);
    k_scanA<<<NBLK, 256>>>();
    k_scanB<<<1, 128>>>();
    k_scanC<<<NBLK, 256>>>();
    k_scatter<<<(NE / 2 + 255) / 256, 256>>>(src, dst);
    k_aggr<0><<<(NN * 32 + 255) / 256, 256>>>(W2, batch);
    k_aggr<1><<<(NN * 32 + 255) / 256, 256>>>(W2, batch);
    k_head<<<(NB + 255) / 256, 256>>>(Wfc, out);
}

// round 4
// speedup vs baseline: 1.0965x; 1.0965x over previous
#include <cuda_runtime.h>
#include <math.h>

#define NN 100000
#define NE 3200000
#define FIN 128
#define RS 16          // padded row stride for 10-dim vectors (64 B, line-aligned)
#define NB 1000
#define NBLK 98        // ceil(NN / 1024) for the two-level scan

// Scratch (allocation-free: __device__ globals)
static __device__ float g_xa[NN * RS];    // x @ W1[:128] (self) ; later unused
static __device__ float g_xb[NN * RS];    // x @ W1[128:] (neighbor) ; later h2
static __device__ float g_h1a[NN * RS];   // h1 @ W2[:10]
static __device__ float g_h1b[NN * RS];   // h1 @ W2[10:]
static __device__ float g_pool[NB * RS];  // batch pool sums ([10] = node count)
static __device__ int   g_deg[NN];        // in-degree
static __device__ int   g_start[NN];      // CSR row starts
static __device__ int   g_cursor[NN];     // scatter cursors
static __device__ int   g_adj[NE];        // CSR adjacency: src ids grouped by dst
static __device__ int   g_bsum[NBLK];

// ---------------------------------------------------------------------------
__global__ void k_zero() {
    int tid = blockIdx.x * blockDim.x + threadIdx.x;
    int stride = gridDim.x * blockDim.x;
    for (int i = tid; i < NN; i += stride) g_deg[i] = 0;
    for (int i = tid; i < NB * RS; i += stride) g_pool[i] = 0.f;
}

// ---------------------------------------------------------------------------
// CSR build: histogram -> 2-level exclusive scan -> scatter
__global__ __launch_bounds__(256) void k_hist(const int* __restrict__ dst) {
    int t = blockIdx.x * blockDim.x + threadIdx.x;
    if (t >= NE / 4) return;
    int4 d4 = __ldg((const int4*)dst + t);
    atomicAdd(&g_deg[d4.x], 1);
    atomicAdd(&g_deg[d4.y], 1);
    atomicAdd(&g_deg[d4.z], 1);
    atomicAdd(&g_deg[d4.w], 1);
}

__global__ __launch_bounds__(256) void k_scanA() {   // per-1024-node block sums
    int t = threadIdx.x, blk = blockIdx.x;
    int base = blk * 1024 + t * 4;
    int s = 0;
#pragma unroll
    for (int j = 0; j < 4; j++) { int i = base + j; if (i < NN) s += g_deg[i]; }
#pragma unroll
    for (int off = 16; off; off >>= 1) s += __shfl_xor_sync(0xffffffffu, s, off);
    __shared__ int ws[8];
    if ((t & 31) == 0) ws[t >> 5] = s;
    __syncthreads();
    if (t == 0) {
        int r = 0;
#pragma unroll
        for (int i = 0; i < 8; i++) r += ws[i];
        g_bsum[blk] = r;
    }
}

__global__ void k_scanB() {                          // exclusive scan of 98 sums
    int t = threadIdx.x;                             // 128 threads
    int v = (t < NBLK) ? g_bsum[t] : 0;
    int lane = t & 31, wid = t >> 5;
    int incl = v;
#pragma unroll
    for (int off = 1; off < 32; off <<= 1) {
        int u = __shfl_up_sync(0xffffffffu, incl, off);
        if (lane >= off) incl += u;
    }
    __shared__ int ws[4], wo[4];
    if (lane == 31) ws[wid] = incl;
    __syncthreads();
    if (t == 0) { int r = 0; for (int i = 0; i < 4; i++) { wo[i] = r; r += ws[i]; } }
    __syncthreads();
    int excl = wo[wid] + incl - v;
    if (t < NBLK) g_bsum[t] = excl;
}

__global__ __launch_bounds__(256) void k_scanC() {   // full scan -> start/cursor
    int t = threadIdx.x, blk = blockIdx.x;
    int base = blk * 1024 + t * 4;
    int vals[4]; int tsum = 0;
#pragma unroll
    for (int j = 0; j < 4; j++) {
        int i = base + j;
        vals[j] = (i < NN) ? g_deg[i] : 0;
        tsum += vals[j];
    }
    int lane = t & 31, wid = t >> 5;
    int incl = tsum;
#pragma unroll
    for (int off = 1; off < 32; off <<= 1) {
        int u = __shfl_up_sync(0xffffffffu, incl, off);
        if (lane >= off) incl += u;
    }
    __shared__ int ws[8], wo[8];
    if (lane == 31) ws[wid] = incl;
    __syncthreads();
    if (t == 0) { int r = 0; for (int i = 0; i < 8; i++) { wo[i] = r; r += ws[i]; } }
    __syncthreads();
    int excl = g_bsum[blk] + wo[wid] + incl - tsum;
#pragma unroll
    for (int j = 0; j < 4; j++) {
        int i = base + j;
        if (i < NN) { g_start[i] = excl; g_cursor[i] = excl; excl += vals[j]; }
    }
}

__global__ __launch_bounds__(256) void k_scatter(const int* __restrict__ src,
                                                 const int* __restrict__ dst) {
    int t = blockIdx.x * blockDim.x + threadIdx.x;
    if (t >= NE / 2) return;
    int2 s2 = __ldg((const int2*)src + t);
    int2 d2 = __ldg((const int2*)dst + t);
    int p0 = atomicAdd(&g_cursor[d2.x], 1);
    int p1 = atomicAdd(&g_cursor[d2.y], 1);
    g_adj[p0] = s2.x;
    g_adj[p1] = s2.y;
}

// ---------------------------------------------------------------------------
// Layer-1 projection (unchanged from round 2): warp per 8 nodes.
__global__ __launch_bounds__(256) void k_gemm1(const float* __restrict__ x,
                                               const float* __restrict__ W1) {
    const int lane = threadIdx.x & 31;
    const int warp = (blockIdx.x * blockDim.x + threadIdx.x) >> 5;
    if (warp >= NN / 8) return;
    const int b4 = (lane >> 4) & 1;
    const int b3 = (lane >> 3) & 1;

    float w[4][20];
#pragma unroll
    for (int j = 0; j < 4; j++) {
        int f = lane * 4 + j;
#pragma unroll
        for (int r = 0; r < 20; r++) {
            int o = (r < 10) ? (10 * b4 + ((r + 5 * b3) % 10))
                             : (10 * (1 - b4) + (((r - 10) + 5 * b3) % 10));
            w[j][r] = __ldg((o < 10) ? &W1[f * 10 + o] : &W1[(f + 128) * 10 + (o - 10)]);
        }
    }

    const int nbase = warp * 8;
#pragma unroll 1
    for (int ni = 0; ni < 8; ni++) {
        int n = nbase + ni;
        float4 xv = *(const float4*)(x + (size_t)n * FIN + lane * 4);
        float xs[4] = {xv.x, xv.y, xv.z, xv.w};
        float acc[20];
#pragma unroll
        for (int r = 0; r < 20; r++) acc[r] = 0.f;
#pragma unroll
        for (int j = 0; j < 4; j++)
#pragma unroll
            for (int r = 0; r < 20; r++) acc[r] += xs[j] * w[j][r];

#pragma unroll
        for (int i = 0; i < 10; i++) acc[i] += __shfl_xor_sync(0xffffffffu, acc[i + 10], 16);
#pragma unroll
        for (int i = 0; i < 5; i++)  acc[i] += __shfl_xor_sync(0xffffffffu, acc[i + 5], 8);
#pragma unroll
        for (int off = 4; off; off >>= 1)
#pragma unroll
            for (int i = 0; i < 5; i++)
                acc[i] += __shfl_xor_sync(0xffffffffu, acc[i], off);

        if ((lane & 7) == 0) {
            if (lane == 0) {
#pragma unroll
                for (int i = 0; i < 5; i++) g_xa[n * RS + i] = acc[i];
            } else if (lane == 8) {
#pragma unroll
                for (int i = 0; i < 5; i++) g_xa[n * RS + 5 + i] = acc[i];
            } else if (lane == 16) {
#pragma unroll
                for (int i = 0; i < 5; i++) g_xb[n * RS + i] = acc[i];
            } else {
#pragma unroll
                for (int i = 0; i < 5; i++) g_xb[n * RS + 5 + i] = acc[i];
            }
        }
    }
}

// ---------------------------------------------------------------------------
__device__ __forceinline__ void red_v4(float* p, float a, float b, float c, float d) {
    asm volatile("red.global.add.v4.f32 [%0], {%1,%2,%3,%4};"
                 :: "l"(p), "f"(a), "f"(b), "f"(c), "f"(d) : "memory");
}

// Pull aggregation, warp per node, COALESCED row gathers:
// lane = (half = edge parity, dim = lane&15). One LDG serves 2 edges (1 line each).
// PASS 0: h1 = relu(xa + mean); h1a/h1b = h1 @ W2 halves (dim-per-lane GEMM).
// PASS 1: h2 = h1a + mean; h2 -> g_xb (pooled later by k_final).
template <int PASS>
__global__ __launch_bounds__(256) void k_aggr(const float* __restrict__ W2) {
    const int lane = threadIdx.x & 31;
    const int n = (blockIdx.x * blockDim.x + threadIdx.x) >> 5;
    if (n >= NN) return;
    const int half = lane >> 4;        // 0/1 = edge parity within a pair
    const int dim  = lane & 15;        // feature dim this lane accumulates

    float wcol[10];
    if (PASS == 0) {                   // lane -> W2 column (cols 0-9 for a/b half)
        int col = dim < 10 ? dim : 0;
#pragma unroll
        for (int k = 0; k < 10; k++) wcol[k] = __ldg(&W2[(k + half * 10) * 10 + col]);
    }

    const int start = g_start[n];
    const int deg   = g_deg[n];
    const float* buf = (PASS == 0) ? g_xb : g_h1b;

    float acc = 0.f;
    for (int base = 0; base < deg; base += 32) {
        int iters = deg - base; if (iters > 32) iters = 32;
        int av = (base + lane < deg) ? __ldg(&g_adj[start + base + lane]) : 0;
        int pairs = (iters + 1) >> 1;
#pragma unroll 4
        for (int it = 0; it < pairs; it++) {
            int e = 2 * it + half;
            int s = __shfl_sync(0xffffffffu, av, e & 31);
            if (e < iters) acc += __ldg(&buf[(size_t)s * RS + dim]);
        }
    }
    acc += __shfl_xor_sync(0xffffffffu, acc, 16);   // combine parities

    const float inv = deg > 0 ? 1.f / (float)deg : 0.f;

    if (PASS == 0) {
        float xs = __ldg(&g_xa[(size_t)n * RS + dim]);
        float h = fmaxf(xs + acc * inv, 0.f);       // valid for dim<10
        float o = 0.f;
#pragma unroll
        for (int k = 0; k < 10; k++)
            o += __shfl_sync(0xffffffffu, h, k) * wcol[k];
        if (dim < 10) {
            if (half == 0) g_h1a[(size_t)n * RS + dim] = o;
            else           g_h1b[(size_t)n * RS + dim] = o;
        }
    } else {
        if (half == 0 && dim < 10) {
            float a = __ldg(&g_h1a[(size_t)n * RS + dim]);
            g_xb[(size_t)n * RS + dim] = a + acc * inv;   // h2
        }
    }
}

// ---------------------------------------------------------------------------
// Pool h2 (in g_xb) by sorted batch id with warp aggregation.
__global__ __launch_bounds__(256) void k_final(const int* __restrict__ batch) {
    int n = blockIdx.x * blockDim.x + threadIdx.x;
    if (n >= NN) return;            // NN % 32 == 0: whole warps exit together
    int lane = threadIdx.x & 31;
    const float4* hr = (const float4*)(g_xb + (size_t)n * RS);
    float4 h0 = __ldg(hr), h1 = __ldg(hr + 1);
    float2 h2 = __ldg((const float2*)(hr + 2));
    float h[10] = {h0.x, h0.y, h0.z, h0.w, h1.x, h1.y, h1.z, h1.w, h2.x, h2.y};
    int b = __ldg(&batch[n]);
    int b0 = __shfl_sync(0xffffffffu, b, 0);
    bool uni = __all_sync(0xffffffffu, b == b0);
    if (uni) {
#pragma unroll
        for (int off = 16; off; off >>= 1)
#pragma unroll
            for (int o = 0; o < 10; o++)
                h[o] += __shfl_xor_sync(0xffffffffu, h[o], off);
        if (lane == 0) {
            float* pp = g_pool + b * RS;
            red_v4(pp,     h[0], h[1], h[2], h[3]);
            red_v4(pp + 4, h[4], h[5], h[6], h[7]);
            red_v4(pp + 8, h[8], h[9], 32.f, 0.f);   // node count rides pad
        }
    } else {
        float* pp = g_pool + b * RS;
#pragma unroll
        for (int o = 0; o < 10; o++) atomicAdd(&pp[o], h[o]);
        atomicAdd(&pp[10], 1.f);
    }
}

// ---------------------------------------------------------------------------
__global__ void k_head(const float* __restrict__ Wfc, float* __restrict__ out) {
    int b = blockIdx.x * blockDim.x + threadIdx.x;
    if (b >= NB) return;
    float inv = 1.f / fmaxf(g_pool[b * RS + 10], 1.f);
    float v = 0.f;
#pragma unroll
    for (int o = 0; o < 10; o++)
        v += g_pool[b * RS + o] * inv * __ldg(&Wfc[o]);
    out[b] = 1.f / (1.f + expf(-v));
}

// ---------------------------------------------------------------------------
extern "C" void kernel_launch(void* const* d_in, const int* in_sizes, int n_in,
                              void* d_out, int out_size) {
    const float* x     = (const float*)d_in[0];
    const int*   ei    = (const int*)d_in[1];   // [2, E]
    const int*   batch = (const int*)d_in[2];
    const float* W1    = (const float*)d_in[3]; // [256,10]
    const float* W2    = (const float*)d_in[4]; // [20,10]
    const float* Wfc   = (const float*)d_in[5]; // [10,1]
    float* out = (float*)d_out;

    const int* src = ei;
    const int* dst = ei + NE;

    k_zero<<<256, 256>>>();
    k_hist<<<(NE / 4 + 255) / 256, 256>>>(dst);
    k_gemm1<<<(NN / 8 + 7) / 8, 256>>>(x, W1);
    k_scanA<<<NBLK, 256>>>();
    k_scanB<<<1, 128>>>();
    k_scanC<<<NBLK, 256>>>();
    k_scatter<<<(NE / 2 + 255) / 256, 256>>>(src, dst);
    k_aggr<0><<<(NN * 32 + 255) / 256, 256>>>(W2);
    k_aggr<1><<<(NN * 32 + 255) / 256, 256>>>(W2);
    k_final<<<(NN + 255) / 256, 256>>>(batch);
    k_head<<<(NB + 255) / 256, 256>>>(Wfc, out);
}

// round 5
// speedup vs baseline: 1.1741x; 1.0707x over previous
#include <cuda_runtime.h>
#include <cuda_fp16.h>
#include <math.h>

#define NN 100000
#define NE 3200000
#define FIN 128
#define RS 16          // fp32 row stride (64 B)
#define RH 8           // half2 per fp16 row (32 B)
#define NB 1000
#define NBLK 98        // ceil(NN / 1024)

// Scratch (allocation-free: __device__ globals)
static __device__ float   g_xa[NN * RS];    // x @ W1[:128] (self, fp32)
static __device__ __half2 g_xbh[NN * RH];   // x @ W1[128:] (neighbor, fp16 rows)
static __device__ float   g_h1a[NN * RS];   // h1 @ W2[:10] (fp32)
static __device__ __half2 g_h1bh[NN * RH];  // h1 @ W2[10:] (fp16 rows)
static __device__ float   g_h2[NN * RS];    // layer-2 output
static __device__ float   g_pool[NB * RS];  // batch pool sums ([10] = node count)
static __device__ int     g_deg[NN];
static __device__ int     g_start[NN];
static __device__ int     g_cursor[NN];
static __device__ int     g_adj[NE];        // CSR adjacency: src grouped by dst
static __device__ int     g_bsum[NBLK];

// ---------------------------------------------------------------------------
__global__ void k_zero() {
    int tid = blockIdx.x * blockDim.x + threadIdx.x;
    int stride = gridDim.x * blockDim.x;
    for (int i = tid; i < NN; i += stride) g_deg[i] = 0;
    for (int i = tid; i < NB * RS; i += stride) g_pool[i] = 0.f;
}

// ---------------------------------------------------------------------------
__global__ __launch_bounds__(256) void k_hist(const int* __restrict__ dst) {
    int t = blockIdx.x * blockDim.x + threadIdx.x;
    if (t >= NE / 4) return;
    int4 d4 = __ldg((const int4*)dst + t);
    atomicAdd(&g_deg[d4.x], 1);
    atomicAdd(&g_deg[d4.y], 1);
    atomicAdd(&g_deg[d4.z], 1);
    atomicAdd(&g_deg[d4.w], 1);
}

__global__ __launch_bounds__(256) void k_scanA() {   // per-1024-node block sums
    int t = threadIdx.x, blk = blockIdx.x;
    int base = blk * 1024 + t * 4;
    int s = 0;
#pragma unroll
    for (int j = 0; j < 4; j++) { int i = base + j; if (i < NN) s += g_deg[i]; }
#pragma unroll
    for (int off = 16; off; off >>= 1) s += __shfl_xor_sync(0xffffffffu, s, off);
    __shared__ int ws[8];
    if ((t & 31) == 0) ws[t >> 5] = s;
    __syncthreads();
    if (t == 0) {
        int r = 0;
#pragma unroll
        for (int i = 0; i < 8; i++) r += ws[i];
        g_bsum[blk] = r;
    }
}

__global__ void k_scanB() {                          // exclusive scan of 98 sums
    int t = threadIdx.x;                             // 128 threads
    int v = (t < NBLK) ? g_bsum[t] : 0;
    int lane = t & 31, wid = t >> 5;
    int incl = v;
#pragma unroll
    for (int off = 1; off < 32; off <<= 1) {
        int u = __shfl_up_sync(0xffffffffu, incl, off);
        if (lane >= off) incl += u;
    }
    __shared__ int ws[4], wo[4];
    if (lane == 31) ws[wid] = incl;
    __syncthreads();
    if (t == 0) { int r = 0; for (int i = 0; i < 4; i++) { wo[i] = r; r += ws[i]; } }
    __syncthreads();
    int excl = wo[wid] + incl - v;
    if (t < NBLK) g_bsum[t] = excl;
}

__global__ __launch_bounds__(256) void k_scanC() {   // full scan -> start/cursor
    int t = threadIdx.x, blk = blockIdx.x;
    int base = blk * 1024 + t * 4;
    int vals[4]; int tsum = 0;
#pragma unroll
    for (int j = 0; j < 4; j++) {
        int i = base + j;
        vals[j] = (i < NN) ? g_deg[i] : 0;
        tsum += vals[j];
    }
    int lane = t & 31, wid = t >> 5;
    int incl = tsum;
#pragma unroll
    for (int off = 1; off < 32; off <<= 1) {
        int u = __shfl_up_sync(0xffffffffu, incl, off);
        if (lane >= off) incl += u;
    }
    __shared__ int ws[8], wo[8];
    if (lane == 31) ws[wid] = incl;
    __syncthreads();
    if (t == 0) { int r = 0; for (int i = 0; i < 8; i++) { wo[i] = r; r += ws[i]; } }
    __syncthreads();
    int excl = g_bsum[blk] + wo[wid] + incl - tsum;
#pragma unroll
    for (int j = 0; j < 4; j++) {
        int i = base + j;
        if (i < NN) { g_start[i] = excl; g_cursor[i] = excl; excl += vals[j]; }
    }
}

__global__ __launch_bounds__(256) void k_scatter(const int* __restrict__ src,
                                                 const int* __restrict__ dst) {
    int t = blockIdx.x * blockDim.x + threadIdx.x;
    if (t >= NE / 2) return;
    int2 s2 = __ldg((const int2*)src + t);
    int2 d2 = __ldg((const int2*)dst + t);
    int p0 = atomicAdd(&g_cursor[d2.x], 1);
    int p1 = atomicAdd(&g_cursor[d2.y], 1);
    g_adj[p0] = s2.x;
    g_adj[p1] = s2.y;
}

// ---------------------------------------------------------------------------
// Layer-1 projection: warp per 8 nodes, permuted split reduction.
// xa stored fp32 (dims 0-4 lane0, 5-9 lane8); xb packed fp16 by lane16.
__global__ __launch_bounds__(256) void k_gemm1(const float* __restrict__ x,
                                               const float* __restrict__ W1) {
    const int lane = threadIdx.x & 31;
    const int warp = (blockIdx.x * blockDim.x + threadIdx.x) >> 5;
    if (warp >= NN / 8) return;
    const int b4 = (lane >> 4) & 1;
    const int b3 = (lane >> 3) & 1;

    float w[4][20];
#pragma unroll
    for (int j = 0; j < 4; j++) {
        int f = lane * 4 + j;
#pragma unroll
        for (int r = 0; r < 20; r++) {
            int o = (r < 10) ? (10 * b4 + ((r + 5 * b3) % 10))
                             : (10 * (1 - b4) + (((r - 10) + 5 * b3) % 10));
            w[j][r] = __ldg((o < 10) ? &W1[f * 10 + o] : &W1[(f + 128) * 10 + (o - 10)]);
        }
    }

    const int nbase = warp * 8;
#pragma unroll 1
    for (int ni = 0; ni < 8; ni++) {
        int n = nbase + ni;
        float4 xv = *(const float4*)(x + (size_t)n * FIN + lane * 4);
        float xs[4] = {xv.x, xv.y, xv.z, xv.w};
        float acc[20];
#pragma unroll
        for (int r = 0; r < 20; r++) acc[r] = 0.f;
#pragma unroll
        for (int j = 0; j < 4; j++)
#pragma unroll
            for (int r = 0; r < 20; r++) acc[r] += xs[j] * w[j][r];

#pragma unroll
        for (int i = 0; i < 10; i++) acc[i] += __shfl_xor_sync(0xffffffffu, acc[i + 10], 16);
#pragma unroll
        for (int i = 0; i < 5; i++)  acc[i] += __shfl_xor_sync(0xffffffffu, acc[i + 5], 8);
#pragma unroll
        for (int off = 4; off; off >>= 1)
#pragma unroll
            for (int i = 0; i < 5; i++)
                acc[i] += __shfl_xor_sync(0xffffffffu, acc[i], off);

        // lane0: xb? -> lane0 holds outs 0-4 (xa), lane8: outs 5-9 (xa),
        // lane16: outs 10-14 (xb dims 0-4), lane24: outs 15-19 (xb dims 5-9).
        float t0 = __shfl_sync(0xffffffffu, acc[0], 24);
        float t1 = __shfl_sync(0xffffffffu, acc[1], 24);
        float t2 = __shfl_sync(0xffffffffu, acc[2], 24);
        float t3 = __shfl_sync(0xffffffffu, acc[3], 24);
        float t4 = __shfl_sync(0xffffffffu, acc[4], 24);

        if (lane == 0) {
#pragma unroll
            for (int i = 0; i < 5; i++) g_xa[n * RS + i] = acc[i];
        } else if (lane == 8) {
#pragma unroll
            for (int i = 0; i < 5; i++) g_xa[n * RS + 5 + i] = acc[i];
        } else if (lane == 16) {
            __half2* row = g_xbh + (size_t)n * RH;
            row[0] = __floats2half2_rn(acc[0], acc[1]);
            row[1] = __floats2half2_rn(acc[2], acc[3]);
            row[2] = __floats2half2_rn(acc[4], t0);
            row[3] = __floats2half2_rn(t1, t2);
            row[4] = __floats2half2_rn(t3, t4);
            __half2 z = __floats2half2_rn(0.f, 0.f);
            row[5] = z; row[6] = z; row[7] = z;
        }
    }
}

// ---------------------------------------------------------------------------
__device__ __forceinline__ void red_v4(float* p, float a, float b, float c, float d) {
    asm volatile("red.global.add.v4.f32 [%0], {%1,%2,%3,%4};"
                 :: "l"(p), "f"(a), "f"(b), "f"(c), "f"(d) : "memory");
}

// Pull aggregation, warp per node, fp16 rows, 4 edges per LDG.
// lane = (q = lane>>3 edge slot, idx = lane&7 half2 slot -> dims 2idx,2idx+1)
template <int PASS>
__global__ __launch_bounds__(256) void k_aggr(const float* __restrict__ W2) {
    const int lane = threadIdx.x & 31;
    const int n = (blockIdx.x * blockDim.x + threadIdx.x) >> 5;
    if (n >= NN) return;
    const int q = lane >> 3;
    const int idx = lane & 7;

    float wcol[10];
    if (PASS == 0) {
        int col = lane & 15; if (col >= 10) col = 0;
        int off = (lane >> 4) * 10;
#pragma unroll
        for (int k = 0; k < 10; k++) wcol[k] = __ldg(&W2[(k + off) * 10 + col]);
    }

    const int start = g_start[n];
    const int deg = g_deg[n];
    const __half2* buf = (PASS == 0) ? g_xbh : g_h1bh;

    float a0 = 0.f, a1 = 0.f;
    for (int base = 0; base < deg; base += 32) {
        int m = deg - base; if (m > 32) m = 32;
        int av = (base + lane < deg) ? __ldg(&g_adj[start + base + lane]) : 0;
        int groups = (m + 3) >> 2;
#pragma unroll 8
        for (int g = 0; g < groups; g++) {
            int e = 4 * g + q;
            int s = __shfl_sync(0xffffffffu, av, e & 31);
            if (e < m) {
                float2 f = __half22float2(__ldg(&buf[(size_t)s * RH + idx]));
                a0 += f.x; a1 += f.y;
            }
        }
    }
    a0 += __shfl_xor_sync(0xffffffffu, a0, 8);
    a0 += __shfl_xor_sync(0xffffffffu, a0, 16);
    a1 += __shfl_xor_sync(0xffffffffu, a1, 8);
    a1 += __shfl_xor_sync(0xffffffffu, a1, 16);

    const float inv = deg > 0 ? 1.f / (float)deg : 0.f;

    if (PASS == 0) {
        float2 xs = *(const float2*)(g_xa + (size_t)n * RS + 2 * idx);
        float h0 = fmaxf(xs.x + a0 * inv, 0.f);   // dim 2*idx
        float h1 = fmaxf(xs.y + a1 * inv, 0.f);   // dim 2*idx+1
        float o = 0.f;
#pragma unroll
        for (int k = 0; k < 10; k++) {
            float hk = (k & 1) ? __shfl_sync(0xffffffffu, h1, k >> 1)
                               : __shfl_sync(0xffffffffu, h0, k >> 1);
            o += hk * wcol[k];
        }
        int dim = lane & 15;
        float onext = __shfl_down_sync(0xffffffffu, o, 1);
        if (lane < 16) {                         // h1a, fp32
            if (dim < 10) g_h1a[(size_t)n * RS + dim] = o;
        } else if ((dim & 1) == 0) {             // h1b, fp16 packed
            __half2 v = (dim < 10) ? __floats2half2_rn(o, onext)
                                   : __floats2half2_rn(0.f, 0.f);
            g_h1bh[(size_t)n * RH + (dim >> 1)] = v;
        }
    } else {
        if (lane < 5) {                          // q==0, idx 0-4 -> dims 0-9
            float2 ar = *(const float2*)(g_h1a + (size_t)n * RS + 2 * idx);
            float2 h2v;
            h2v.x = ar.x + a0 * inv;
            h2v.y = ar.y + a1 * inv;
            *(float2*)(g_h2 + (size_t)n * RS + 2 * idx) = h2v;
        }
    }
}

// ---------------------------------------------------------------------------
// Pool h2 by sorted batch id with warp aggregation.
__global__ __launch_bounds__(256) void k_final(const int* __restrict__ batch) {
    int n = blockIdx.x * blockDim.x + threadIdx.x;
    if (n >= NN) return;            // NN % 32 == 0
    int lane = threadIdx.x & 31;
    const float4* hr = (const float4*)(g_h2 + (size_t)n * RS);
    float4 h0 = __ldg(hr), h1 = __ldg(hr + 1);
    float2 h2 = __ldg((const float2*)(hr + 2));
    float h[10] = {h0.x, h0.y, h0.z, h0.w, h1.x, h1.y, h1.z, h1.w, h2.x, h2.y};
    int b = __ldg(&batch[n]);
    int b0 = __shfl_sync(0xffffffffu, b, 0);
    bool uni = __all_sync(0xffffffffu, b == b0);
    if (uni) {
#pragma unroll
        for (int off = 16; off; off >>= 1)
#pragma unroll
            for (int o = 0; o < 10; o++)
                h[o] += __shfl_xor_sync(0xffffffffu, h[o], off);
        if (lane == 0) {
            float* pp = g_pool + b * RS;
            red_v4(pp,     h[0], h[1], h[2], h[3]);
            red_v4(pp + 4, h[4], h[5], h[6], h[7]);
            red_v4(pp + 8, h[8], h[9], 32.f, 0.f);
        }
    } else {
        float* pp = g_pool + b * RS;
#pragma unroll
        for (int o = 0; o < 10; o++) atomicAdd(&pp[o], h[o]);
        atomicAdd(&pp[10], 1.f);
    }
}

// ---------------------------------------------------------------------------
__global__ void k_head(const float* __restrict__ Wfc, float* __restrict__ out) {
    int b = blockIdx.x * blockDim.x + threadIdx.x;
    if (b >= NB) return;
    float inv = 1.f / fmaxf(g_pool[b * RS + 10], 1.f);
    float v = 0.f;
#pragma unroll
    for (int o = 0; o < 10; o++)
        v += g_pool[b * RS + o] * inv * __ldg(&Wfc[o]);
    out[b] = 1.f / (1.f + expf(-v));
}

// ---------------------------------------------------------------------------
extern "C" void kernel_launch(void* const* d_in, const int* in_sizes, int n_in,
                              void* d_out, int out_size) {
    const float* x     = (const float*)d_in[0];
    const int*   ei    = (const int*)d_in[1];   // [2, E]
    const int*   batch = (const int*)d_in[2];
    const float* W1    = (const float*)d_in[3]; // [256,10]
    const float* W2    = (const float*)d_in[4]; // [20,10]
    const float* Wfc   = (const float*)d_in[5]; // [10,1]
    float* out = (float*)d_out;

    const int* src = ei;
    const int* dst = ei + NE;

    // launch order puts k_gemm1 at position 3 (0-based) so ncu -s5 -c1 lands on it
    k_zero<<<256, 256>>>();
    k_hist<<<(NE / 4 + 255) / 256, 256>>>(dst);
    k_scanA<<<NBLK, 256>>>();
    k_gemm1<<<(NN / 8 + 7) / 8, 256>>>(x, W1);
    k_scanB<<<1, 128>>>();
    k_scanC<<<NBLK, 256>>>();
    k_scatter<<<(NE / 2 + 255) / 256, 256>>>(src, dst);
    k_aggr<0><<<(NN * 32 + 255) / 256, 256>>>(W2);
    k_aggr<1><<<(NN * 32 + 255) / 256, 256>>>(W2);
    k_final<<<(NN + 255) / 256, 256>>>(batch);
    k_head<<<(NB + 255) / 256, 256>>>(Wfc, out);
}

// round 7
// speedup vs baseline: 1.3758x; 1.1718x over previous
#include <cuda_runtime.h>
#include <cuda_fp16.h>
#include <math.h>
#include <string.h>

#define NN 100000
#define NE 3200000
#define FIN 128
#define RS 16          // fp32 row stride (64 B)
#define RH 8           // half2 per fp16 row (32 B)
#define NB 1000
#define NBLK 98        // ceil(NN / 1024)
#define SCAT_BLOCKS ((NE / 2 + 255) / 256)
#define GEMM_BLOCKS ((NN + 255) / 256)

// Scratch (allocation-free: __device__ globals)
static __device__ float   g_xa[NN * RS];    // x @ W1[:128] (self, fp32)
static __device__ __half2 g_xbh[NN * RH];   // x @ W1[128:] (neighbor, fp16)
static __device__ float   g_h1a[NN * RS];   // h1 @ W2[:10] (fp32)
static __device__ __half2 g_h1bh[NN * RH];  // h1 @ W2[10:] (fp16)
static __device__ float   g_h2[NN * RS];    // layer-2 output
static __device__ float   g_pool[NB * RS];  // batch pool sums ([10] = count)
static __device__ int     g_deg[NN];
static __device__ int     g_start[NN];
static __device__ int     g_cursor[NN];
static __device__ int     g_adj[NE];        // CSR adjacency: src grouped by dst
static __device__ int     g_bsum[NBLK];

__device__ __forceinline__ unsigned h2u(__half2 h) {
    unsigned u;
    memcpy(&u, &h, 4);
    return u;
}

// ---------------------------------------------------------------------------
__global__ void k_zero() {
    int tid = blockIdx.x * blockDim.x + threadIdx.x;
    int stride = gridDim.x * blockDim.x;
    for (int i = tid; i < NN; i += stride) g_deg[i] = 0;
    for (int i = tid; i < NB * RS; i += stride) g_pool[i] = 0.f;
}

// ---------------------------------------------------------------------------
__global__ __launch_bounds__(256) void k_hist(const int* __restrict__ dst) {
    int t = blockIdx.x * blockDim.x + threadIdx.x;
    if (t >= NE / 4) return;
    int4 d4 = __ldg((const int4*)dst + t);
    atomicAdd(&g_deg[d4.x], 1);
    atomicAdd(&g_deg[d4.y], 1);
    atomicAdd(&g_deg[d4.z], 1);
    atomicAdd(&g_deg[d4.w], 1);
}

__global__ __launch_bounds__(256) void k_scanA() {   // per-1024-node block sums
    int t = threadIdx.x, blk = blockIdx.x;
    int base = blk * 1024 + t * 4;
    int s = 0;
#pragma unroll
    for (int j = 0; j < 4; j++) { int i = base + j; if (i < NN) s += g_deg[i]; }
#pragma unroll
    for (int off = 16; off; off >>= 1) s += __shfl_xor_sync(0xffffffffu, s, off);
    __shared__ int ws[8];
    if ((t & 31) == 0) ws[t >> 5] = s;
    __syncthreads();
    if (t == 0) {
        int r = 0;
#pragma unroll
        for (int i = 0; i < 8; i++) r += ws[i];
        g_bsum[blk] = r;
    }
}

// scanC with inlined cross-block prefix (scanB folded in)
__global__ __launch_bounds__(256) void k_scanC() {
    int t = threadIdx.x, blk = blockIdx.x;
    __shared__ int s_pre;
    if (t < 32) {
        int pre = 0;
        for (int i = t; i < blk; i += 32) pre += g_bsum[i];
#pragma unroll
        for (int off = 16; off; off >>= 1) pre += __shfl_xor_sync(0xffffffffu, pre, off);
        if (t == 0) s_pre = pre;
    }
    __syncthreads();
    int base = blk * 1024 + t * 4;
    int vals[4]; int tsum = 0;
#pragma unroll
    for (int j = 0; j < 4; j++) {
        int i = base + j;
        vals[j] = (i < NN) ? g_deg[i] : 0;
        tsum += vals[j];
    }
    int lane = t & 31, wid = t >> 5;
    int incl = tsum;
#pragma unroll
    for (int off = 1; off < 32; off <<= 1) {
        int u = __shfl_up_sync(0xffffffffu, incl, off);
        if (lane >= off) incl += u;
    }
    __shared__ int ws[8], wo[8];
    if (lane == 31) ws[wid] = incl;
    __syncthreads();
    if (t == 0) { int r = 0; for (int i = 0; i < 8; i++) { wo[i] = r; r += ws[i]; } }
    __syncthreads();
    int excl = s_pre + wo[wid] + incl - tsum;
#pragma unroll
    for (int j = 0; j < 4; j++) {
        int i = base + j;
        if (i < NN) { g_start[i] = excl; g_cursor[i] = excl; excl += vals[j]; }
    }
}

// ---------------------------------------------------------------------------
// Fused: blocks [0, SCAT_BLOCKS) scatter edges; rest run layer-1 GEMM
// (thread-per-node, transposed weights in smem, zero shuffles).
__global__ __launch_bounds__(256) void k_scatter_gemm(const int* __restrict__ src,
                                                      const int* __restrict__ dst,
                                                      const float* __restrict__ x,
                                                      const float* __restrict__ W1) {
    if (blockIdx.x < SCAT_BLOCKS) {
        int t = blockIdx.x * 256 + threadIdx.x;
        if (t >= NE / 2) return;
        int2 s2 = __ldg((const int2*)src + t);
        int2 d2 = __ldg((const int2*)dst + t);
        int p0 = atomicAdd(&g_cursor[d2.x], 1);
        int p1 = atomicAdd(&g_cursor[d2.y], 1);
        g_adj[p0] = s2.x;
        g_adj[p1] = s2.y;
        return;
    }
    // ---- GEMM path ----
    __shared__ float sw[20 * 128];     // wt[o][f]: o<10 -> W1[:128], o>=10 -> W1[128:]
    int tid = threadIdx.x;
    for (int i = tid; i < 2560; i += 256) {
        int o = i >> 7, f = i & 127;
        sw[i] = (o < 10) ? __ldg(&W1[f * 10 + o]) : __ldg(&W1[(f + 128) * 10 + (o - 10)]);
    }
    __syncthreads();
    int n = (blockIdx.x - SCAT_BLOCKS) * 256 + tid;
    if (n >= NN) return;
    const float4* xr = (const float4*)(x + (size_t)n * FIN);
    const float4* swt = (const float4*)sw;    // swt[o*32 + k4]
    float acc[20];
#pragma unroll
    for (int o = 0; o < 20; o++) acc[o] = 0.f;
#pragma unroll 4
    for (int k4 = 0; k4 < 32; k4++) {
        float4 xv = __ldg(xr + k4);
#pragma unroll
        for (int o = 0; o < 20; o++) {
            float4 w = swt[o * 32 + k4];
            acc[o] = fmaf(xv.x, w.x, acc[o]);
            acc[o] = fmaf(xv.y, w.y, acc[o]);
            acc[o] = fmaf(xv.z, w.z, acc[o]);
            acc[o] = fmaf(xv.w, w.w, acc[o]);
        }
    }
    float* pa = g_xa + (size_t)n * RS;
    *(float4*)(pa)     = make_float4(acc[0], acc[1], acc[2], acc[3]);
    *(float4*)(pa + 4) = make_float4(acc[4], acc[5], acc[6], acc[7]);
    *(float2*)(pa + 8) = make_float2(acc[8], acc[9]);
    uint4 u;
    u.x = h2u(__floats2half2_rn(acc[10], acc[11]));
    u.y = h2u(__floats2half2_rn(acc[12], acc[13]));
    u.z = h2u(__floats2half2_rn(acc[14], acc[15]));
    u.w = h2u(__floats2half2_rn(acc[16], acc[17]));
    *(uint4*)(g_xbh + (size_t)n * RH) = u;
    ((unsigned*)(g_xbh + (size_t)n * RH))[4] = h2u(__floats2half2_rn(acc[18], acc[19]));
}

// ---------------------------------------------------------------------------
__device__ __forceinline__ void red_v4(float* p, float a, float b, float c, float d) {
    asm volatile("red.global.add.v4.f32 [%0], {%1,%2,%3,%4};"
                 :: "l"(p), "f"(a), "f"(b), "f"(c), "f"(d) : "memory");
}

// Pull aggregation, warp per node, fp16 rows, 4 edges per LDG.
// lane = (q = lane>>3 edge slot, idx = lane&7 -> dims 2idx, 2idx+1)
template <int PASS>
__global__ __launch_bounds__(256) void k_aggr(const float* __restrict__ W2) {
    const int lane = threadIdx.x & 31;
    const int n = (blockIdx.x * blockDim.x + threadIdx.x) >> 5;
    if (n >= NN) return;
    const int q = lane >> 3;
    const int idx = lane & 7;

    float wcol[10];
    if (PASS == 0) {
        int col = lane & 15; if (col >= 10) col = 0;
        int off = (lane >> 4) * 10;
#pragma unroll
        for (int k = 0; k < 10; k++) wcol[k] = __ldg(&W2[(k + off) * 10 + col]);
    }

    const int start = g_start[n];
    const int deg = g_deg[n];
    const __half2* buf = (PASS == 0) ? g_xbh : g_h1bh;

    float a0 = 0.f, a1 = 0.f;
    for (int base = 0; base < deg; base += 32) {
        int m = deg - base; if (m > 32) m = 32;
        int av = (base + lane < deg) ? __ldg(&g_adj[start + base + lane]) : 0;
        int groups = (m + 3) >> 2;
#pragma unroll 8
        for (int g = 0; g < groups; g++) {
            int e = 4 * g + q;
            int s = __shfl_sync(0xffffffffu, av, e & 31);
            if (e < m) {
                float2 f = __half22float2(__ldg(&buf[(size_t)s * RH + idx]));
                a0 += f.x; a1 += f.y;
            }
        }
    }
    a0 += __shfl_xor_sync(0xffffffffu, a0, 8);
    a0 += __shfl_xor_sync(0xffffffffu, a0, 16);
    a1 += __shfl_xor_sync(0xffffffffu, a1, 8);
    a1 += __shfl_xor_sync(0xffffffffu, a1, 16);

    const float inv = deg > 0 ? 1.f / (float)deg : 0.f;

    if (PASS == 0) {
        float2 xs = *(const float2*)(g_xa + (size_t)n * RS + 2 * idx);
        float h0 = fmaxf(xs.x + a0 * inv, 0.f);   // dim 2*idx
        float h1 = fmaxf(xs.y + a1 * inv, 0.f);   // dim 2*idx+1
        float o = 0.f;
#pragma unroll
        for (int k = 0; k < 10; k++) {
            float hk = (k & 1) ? __shfl_sync(0xffffffffu, h1, k >> 1)
                               : __shfl_sync(0xffffffffu, h0, k >> 1);
            o += hk * wcol[k];
        }
        int dim = lane & 15;
        float onext = __shfl_down_sync(0xffffffffu, o, 1);
        if (lane < 16) {                         // h1a, fp32
            if (dim < 10) g_h1a[(size_t)n * RS + dim] = o;
        } else if ((dim & 1) == 0 && dim < 10) { // h1b, fp16 packed
            g_h1bh[(size_t)n * RH + (dim >> 1)] = __floats2half2_rn(o, onext);
        }
    } else {
        if (lane < 5) {                          // q==0, idx 0-4 -> dims 0-9
            float2 ar = *(const float2*)(g_h1a + (size_t)n * RS + 2 * idx);
            float2 h2v;
            h2v.x = ar.x + a0 * inv;
            h2v.y = ar.y + a1 * inv;
            *(float2*)(g_h2 + (size_t)n * RS + 2 * idx) = h2v;
        }
    }
}

// ---------------------------------------------------------------------------
// Pool h2 by sorted batch id with warp aggregation.
__global__ __launch_bounds__(256) void k_final(const int* __restrict__ batch) {
    int n = blockIdx.x * blockDim.x + threadIdx.x;
    if (n >= NN) return;            // NN % 32 == 0
    int lane = threadIdx.x & 31;
    const float4* hr = (const float4*)(g_h2 + (size_t)n * RS);
    float4 h0 = __ldg(hr), h1 = __ldg(hr + 1);
    float2 h2 = __ldg((const float2*)(hr + 2));
    float h[10] = {h0.x, h0.y, h0.z, h0.w, h1.x, h1.y, h1.z, h1.w, h2.x, h2.y};
    int b = __ldg(&batch[n]);
    int b0 = __shfl_sync(0xffffffffu, b, 0);
    bool uni = __all_sync(0xffffffffu, b == b0);
    if (uni) {
#pragma unroll
        for (int off = 16; off; off >>= 1)
#pragma unroll
            for (int o = 0; o < 10; o++)
                h[o] += __shfl_xor_sync(0xffffffffu, h[o], off);
        if (lane == 0) {
            float* pp = g_pool + b * RS;
            red_v4(pp,     h[0], h[1], h[2], h[3]);
            red_v4(pp + 4, h[4], h[5], h[6], h[7]);
            red_v4(pp + 8, h[8], h[9], 32.f, 0.f);
        }
    } else {
        float* pp = g_pool + b * RS;
#pragma unroll
        for (int o = 0; o < 10; o++) atomicAdd(&pp[o], h[o]);
        atomicAdd(&pp[10], 1.f);
    }
}

// ---------------------------------------------------------------------------
__global__ void k_head(const float* __restrict__ Wfc, float* __restrict__ out) {
    int b = blockIdx.x * blockDim.x + threadIdx.x;
    if (b >= NB) return;
    float inv = 1.f / fmaxf(g_pool[b * RS + 10], 1.f);
    float v = 0.f;
#pragma unroll
    for (int o = 0; o < 10; o++)
        v += g_pool[b * RS + o] * inv * __ldg(&Wfc[o]);
    out[b] = 1.f / (1.f + expf(-v));
}

// ---------------------------------------------------------------------------
extern "C" void kernel_launch(void* const* d_in, const int* in_sizes, int n_in,
                              void* d_out, int out_size) {
    const float* x     = (const float*)d_in[0];
    const int*   ei    = (const int*)d_in[1];   // [2, E]
    const int*   batch = (const int*)d_in[2];
    const float* W1    = (const float*)d_in[3]; // [256,10]
    const float* W2    = (const float*)d_in[4]; // [20,10]
    const float* Wfc   = (const float*)d_in[5]; // [10,1]
    float* out = (float*)d_out;

    const int* src = ei;
    const int* dst = ei + NE;

    k_zero<<<256, 256>>>();
    k_hist<<<(NE / 4 + 255) / 256, 256>>>(dst);
    k_scanA<<<NBLK, 256>>>();
    k_scanC<<<NBLK, 256>>>();
    k_scatter_gemm<<<SCAT_BLOCKS + GEMM_BLOCKS, 256>>>(src, dst, x, W1);
    k_aggr<0><<<(NN * 32 + 255) / 256, 256>>>(W2);
    k_aggr<1><<<(NN * 32 + 255) / 256, 256>>>(W2);
    k_final<<<(NN + 255) / 256, 256>>>(batch);
    k_head<<<(NB + 255) / 256, 256>>>(Wfc, out);
}